// round 6
// baseline (speedup 1.0000x reference)
#include <cuda_runtime.h>

#define NP 8192
#define NQ (2*NP)

__device__ __align__(16) float g_U[NQ*128];
__device__ float g_cmin[NQ*16];
__device__ unsigned long long g_surv[(long)NQ*128];
__device__ int   g_qcnt[NQ];
__device__ int   g_knn[NQ*16];
__device__ __align__(16) float g_wu [64*128];
__device__ __align__(16) float g_w1t[64*64];
__device__ __align__(16) float g_w2t[64*128];

__device__ __forceinline__ float leaky(float v){ return fmaxf(v, 0.2f*v); }
__device__ __forceinline__ float distp(float xi,float yi,float zi,const float4 c){
    return fmaf(zi,c.z,fmaf(yi,c.y,fmaf(xi,c.x,c.w)));
}
__device__ __forceinline__ unsigned int okey(float d){
    unsigned int u = __float_as_uint(d);
    u ^= ((unsigned int)((int)u >> 31)) | 0x80000000u;
    return u;
}
__device__ __forceinline__ void fma2(unsigned long long &acc, unsigned long long a, unsigned long long b){
    asm("fma.rn.f32x2 %0, %1, %2, %3;" : "=l"(acc) : "l"(a), "l"(b), "l"(acc));
}
__device__ __forceinline__ unsigned long long splat2(float v){
    unsigned long long r;
    asm("mov.b64 %0, {%1, %1};" : "=l"(r) : "f"(v));
    return r;
}
__device__ __forceinline__ void unpack2(unsigned long long v, float &lo, float &hi){
    asm("mov.b64 {%0, %1}, %2;" : "=f"(lo), "=f"(hi) : "l"(v));
}
__device__ __forceinline__ unsigned long long umin64(unsigned long long a, unsigned long long b){
    return a < b ? a : b;
}

// ---------------- prep: transpose weights + zero counters ----------------
__global__ void prep_kernel(const float* __restrict__ Wn, const float* __restrict__ We,
                            const float* __restrict__ W1, const float* __restrict__ W2){
    int i = blockIdx.x*blockDim.x + threadIdx.x;
    if (i < NQ) g_qcnt[i] = 0;
    if (i < 8192){
        int c = i >> 7, o = i & 127;
        g_wu[i] = (o < 64) ? Wn[o*64 + c] : We[(o-64)*64 + c];
    } else if (i < 12288){
        int j = i - 8192; int c = j >> 6, o = j & 63;
        g_w1t[j] = W1[o*64 + c];
    } else if (i < 20480){
        int j = i - 12288; int c = j >> 7, o = j & 127;
        g_w2t[j] = W2[o*64 + c];
    }
}

// ---------- KNN pass 1: branchless chunk-mins, thread = (query, quarter of 2048) ----------
__global__ void knn_pass1(const float* __restrict__ pos){
    __shared__ float4 tile[256];
    int bx = blockIdx.x;
    int b  = bx >> 7;
    int r  = bx & 127;
    int quarter = r >> 5;
    int n  = (r & 31)*256 + threadIdx.x;
    const float* pb = pos + b*NP*3;
    float xi = pb[n*3+0], yi = pb[n*3+1], zi = pb[n*3+2];
    long obase = ((long)(b*NP + n))*16 + quarter*4;

#pragma unroll
    for (int c4 = 0; c4 < 4; c4++){
        float mA = 3.4e38f, mB = 3.4e38f;
#pragma unroll
        for (int t2 = 0; t2 < 2; t2++){
            int jb = quarter*2048 + c4*512 + t2*256;
            int j  = jb + threadIdx.x;
            float x = pb[j*3+0], y = pb[j*3+1], z = pb[j*3+2];
            float sq = x*x; sq = fmaf(y,y,sq); sq = fmaf(z,z,sq);
            __syncthreads();
            tile[threadIdx.x] = make_float4(-2.0f*x, -2.0f*y, -2.0f*z, sq);
            __syncthreads();
#pragma unroll 8
            for (int jj = 0; jj < 256; jj += 4){
                float d0 = distp(xi,yi,zi, tile[jj+0]);
                float d1 = distp(xi,yi,zi, tile[jj+1]);
                float d2 = distp(xi,yi,zi, tile[jj+2]);
                float d3 = distp(xi,yi,zi, tile[jj+3]);
                mA = fminf(mA, fminf(d0,d1));
                mB = fminf(mB, fminf(d2,d3));
            }
        }
        g_cmin[obase + c4] = fminf(mA, mB);
    }
}

// ---------- KNN pass 2: filtered scan, atomic append to per-query list ----------
__global__ void knn_pass2(const float* __restrict__ pos){
    __shared__ float4 tile[256];
    int bx  = blockIdx.x;             // 512 blocks
    int seg = bx & 7;
    int q   = (bx >> 3)*256 + threadIdx.x;
    int b   = q >> 13;
    int n   = q & 8191;
    const float* pb = pos + b*NP*3;
    float xi = pb[n*3+0], yi = pb[n*3+1], zi = pb[n*3+2];

    float T0 = -3.4e38f;
#pragma unroll
    for (int s = 0; s < 16; s++) T0 = fmaxf(T0, g_cmin[(long)q*16 + s]);

#pragma unroll
    for (int t = 0; t < 4; t++){
        int jb = seg*1024 + t*256;
        int j  = jb + threadIdx.x;
        float x = pb[j*3+0], y = pb[j*3+1], z = pb[j*3+2];
        float sq = x*x; sq = fmaf(y,y,sq); sq = fmaf(z,z,sq);
        __syncthreads();
        tile[threadIdx.x] = make_float4(-2.0f*x, -2.0f*y, -2.0f*z, sq);
        __syncthreads();
        for (int jj = 0; jj < 256; jj += 4){
            float d0 = distp(xi,yi,zi, tile[jj+0]);
            float d1 = distp(xi,yi,zi, tile[jj+1]);
            float d2 = distp(xi,yi,zi, tile[jj+2]);
            float d3 = distp(xi,yi,zi, tile[jj+3]);
            float mn = fminf(fminf(d0,d1), fminf(d2,d3));
            if (mn <= T0){
                float dd[4] = {d0,d1,d2,d3};
#pragma unroll
                for (int u = 0; u < 4; u++){
                    if (dd[u] <= T0){
                        int slot = atomicAdd(&g_qcnt[q], 1);
                        if (slot < 128)
                            g_surv[(long)q*128 + slot] =
                                ((unsigned long long)okey(dd[u]) << 32) | (unsigned int)(jb + jj + u);
                    }
                }
            }
        }
    }
}

// ---------- KNN pass 3: warp/query, register keys, 16 warp-min rounds ----------
__global__ void knn_pass3(const float* __restrict__ pos){
    int w    = threadIdx.x >> 5;
    int lane = threadIdx.x & 31;
    int q    = blockIdx.x*8 + w;       // 2048 blocks x 8 warps

    int cnt = g_qcnt[q];
    if (cnt <= 128){
        unsigned long long k[4];
#pragma unroll
        for (int u = 0; u < 4; u++){
            int t = lane + u*32;
            k[u] = (t < cnt) ? g_surv[(long)q*128 + t] : ~0ull;
        }
        for (int r = 0; r < 16; r++){
            unsigned long long best = umin64(umin64(k[0],k[1]), umin64(k[2],k[3]));
            unsigned long long rb = best;
#pragma unroll
            for (int o = 16; o; o >>= 1)
                rb = umin64(rb, __shfl_down_sync(0xffffffff, rb, o));
            rb = __shfl_sync(0xffffffff, rb, 0);
            if (lane == 0) g_knn[(long)q*16 + r] = (int)(rb & 0xffffffffull);
            if (best == rb){
#pragma unroll
                for (int u = 0; u < 4; u++) if (k[u] == rb) k[u] = ~0ull;
            }
        }
    } else if (lane == 0){
        // exact full rescan fallback (statistically never taken)
        int b = q >> 13, n = q & 8191;
        const float* pb = pos + b*NP*3;
        float xi = pb[n*3+0], yi = pb[n*3+1], zi = pb[n*3+2];
        unsigned long long bk[16];
#pragma unroll
        for (int s = 0; s < 16; s++) bk[s] = ~0ull;
        unsigned long long worst = ~0ull; int ws = 0;
        for (int j = 0; j < NP; j++){
            float x = pb[j*3+0], y = pb[j*3+1], z = pb[j*3+2];
            float sq = x*x; sq = fmaf(y,y,sq); sq = fmaf(z,z,sq);
            float d = fmaf(zi,-2.0f*z, fmaf(yi,-2.0f*y, fmaf(xi,-2.0f*x, sq)));
            unsigned long long key = ((unsigned long long)okey(d) << 32) | (unsigned int)j;
            if (key < worst){
                bk[ws] = key;
                worst = bk[0]; ws = 0;
                for (int s = 1; s < 16; s++) if (bk[s] > worst){ worst = bk[s]; ws = s; }
            }
        }
        for (int rr = 0; rr < 16; rr++){
            unsigned long long best = ~0ull; int bj = 0;
            for (int s = 0; s < 16; s++) if (bk[s] < best){ best = bk[s]; bj = s; }
            bk[bj] = ~0ull;
            g_knn[(long)q*16 + rr] = (int)(best & 0xffffffffull);
        }
    }
}

// ---------------- U = [W_node; W_edge] * feat ----------------
__global__ void u_kernel(const float* __restrict__ feat){
    extern __shared__ float smC[];
    float* fs = smC;
    float* ws = smC + 64*128;
    int q0 = blockIdx.x*128;
    int b  = q0 >> 13;
    int n0 = q0 & 8191;
    for (int i=threadIdx.x; i<64*128; i+=256){
        int c = i>>7, nn = i&127;
        fs[i] = feat[((long)(b*64 + c))*NP + n0 + nn];
        ws[i] = g_wu[i];
    }
    __syncthreads();
    int tx = threadIdx.x & 15, ty = threadIdx.x >> 4;
    float acc[8][8];
#pragma unroll
    for (int i=0;i<8;i++)
#pragma unroll
        for (int j=0;j<8;j++) acc[i][j]=0.f;
#pragma unroll 4
    for (int c=0;c<64;c++){
        float4 a0 = *(const float4*)&fs[c*128 + ty*8];
        float4 a1 = *(const float4*)&fs[c*128 + ty*8 + 4];
        float4 w0 = *(const float4*)&ws[c*128 + tx*8];
        float4 w1 = *(const float4*)&ws[c*128 + tx*8 + 4];
        float av[8] = {a0.x,a0.y,a0.z,a0.w,a1.x,a1.y,a1.z,a1.w};
        float bv[8] = {w0.x,w0.y,w0.z,w0.w,w1.x,w1.y,w1.z,w1.w};
#pragma unroll
        for (int i=0;i<8;i++)
#pragma unroll
            for (int j=0;j<8;j++) acc[i][j] = fmaf(av[i], bv[j], acc[i][j]);
    }
#pragma unroll
    for (int i=0;i<8;i++){
        long q = q0 + ty*8 + i;
        float* r = &g_U[q*128 + tx*8];
        *(float4*)r     = make_float4(acc[i][0],acc[i][1],acc[i][2],acc[i][3]);
        *(float4*)(r+4) = make_float4(acc[i][4],acc[i][5],acc[i][6],acc[i][7]);
    }
}

// ---------------- fused gather + h1 + m1 + m2 + maxpool (f32x2 GEMMs) ----------------
__global__ void __launch_bounds__(256, 2)
edge_main(const float* __restrict__ bn,  const float* __restrict__ be,
          const float* __restrict__ vb1, const float* __restrict__ vb2,
          float* __restrict__ out){
    extern __shared__ float sm[];
    float* h1T = sm;                  // [64][136], reused as h2T
    float* w1s = h1T + 64*136;
    float* w2s = w1s + 64*64;
    float* uec = w2s + 64*128;
    float* red = uec + 512;
    float* bns = red + 2048;
    float* bes = bns + 64;
    float* b1s = bes + 64;
    float* b2s = b1s + 64;
    int*   idxs = (int*)(b2s + 128);

    int q0 = blockIdx.x*8;
    int b  = q0 >> 13;
    int n0 = q0 & 8191;
    int tid = threadIdx.x;

    for (int i=tid;i<4096;i+=256) w1s[i] = g_w1t[i];
    for (int i=tid;i<8192;i+=256) w2s[i] = g_w2t[i];
    if (tid<64){ bns[tid]=bn[tid]; bes[tid]=be[tid]; b1s[tid]=vb1[tid]; }
    if (tid<128) b2s[tid]=vb2[tid];
    if (tid<128) idxs[tid] = g_knn[(long)q0*16 + tid];
    for (int i=tid;i<512;i+=256){ int p=i>>6, j=i&63; uec[i] = g_U[(long)(q0+p)*128 + 64 + j]; }
    __syncthreads();

    { // stage A: gather + layer1 -> h1T[j][m]
        int m  = tid >> 1;
        int jb = (tid & 1) * 32;
        int p  = m >> 4;
        int nb = idxs[m];
        const float* Ur = &g_U[(long)((b<<13) + nb)*128];
#pragma unroll
        for (int v=0; v<8; v++){
            float4 un = *(const float4*)&Ur[jb + v*4];
            float4 ue = *(const float4*)&Ur[64 + jb + v*4];
            float unv[4] = {un.x,un.y,un.z,un.w};
            float uev[4] = {ue.x,ue.y,ue.z,ue.w};
#pragma unroll
            for (int e=0;e<4;e++){
                int j = jb + v*4 + e;
                float a = leaky(unv[e] + bns[j]);
                float c = leaky(uev[e] - uec[p*64 + j] + bes[j]);
                h1T[j*136 + m] = a + c;
            }
        }
    }
    __syncthreads();

    int tx = tid & 15, ty = tid >> 4;

    { // stage B: M=128 N=64 K=64, f32x2 packed along m
        unsigned long long acc2[4][4];
#pragma unroll
        for (int i=0;i<4;i++)
#pragma unroll
            for (int o=0;o<4;o++) acc2[i][o]=0ull;
#pragma unroll 4
        for (int c=0;c<64;c++){
            ulonglong2 a01 = *(const ulonglong2*)&h1T[c*136 + ty*8];
            ulonglong2 a23 = *(const ulonglong2*)&h1T[c*136 + ty*8 + 4];
            float4 wv = *(const float4*)&w1s[c*64 + tx*4];
            unsigned long long av[4] = {a01.x, a01.y, a23.x, a23.y};
            unsigned long long bs[4] = {splat2(wv.x), splat2(wv.y), splat2(wv.z), splat2(wv.w)};
#pragma unroll
            for (int i=0;i<4;i++)
#pragma unroll
                for (int o=0;o<4;o++) fma2(acc2[i][o], av[i], bs[o]);
        }
        __syncthreads();
#pragma unroll
        for (int i=0;i<4;i++){
            int m = ty*8 + i*2;
#pragma unroll
            for (int o=0;o<4;o++){
                float lo, hi; unpack2(acc2[i][o], lo, hi);
                float bias = b1s[tx*4+o];
                h1T[(tx*4+o)*136 + m]     = leaky(lo + bias);
                h1T[(tx*4+o)*136 + m + 1] = leaky(hi + bias);
            }
        }
    }
    __syncthreads();

    { // stage C: M=128 N=128 K=64, f32x2 + partial max
        unsigned long long acc2[4][8];
#pragma unroll
        for (int i=0;i<4;i++)
#pragma unroll
            for (int o=0;o<8;o++) acc2[i][o]=0ull;
#pragma unroll 4
        for (int c=0;c<64;c++){
            ulonglong2 a01 = *(const ulonglong2*)&h1T[c*136 + ty*8];
            ulonglong2 a23 = *(const ulonglong2*)&h1T[c*136 + ty*8 + 4];
            float4 w0 = *(const float4*)&w2s[c*128 + tx*8];
            float4 w1 = *(const float4*)&w2s[c*128 + tx*8 + 4];
            unsigned long long av[4] = {a01.x, a01.y, a23.x, a23.y};
            unsigned long long bs[8] = {splat2(w0.x), splat2(w0.y), splat2(w0.z), splat2(w0.w),
                                        splat2(w1.x), splat2(w1.y), splat2(w1.z), splat2(w1.w)};
#pragma unroll
            for (int i=0;i<4;i++)
#pragma unroll
                for (int o=0;o<8;o++) fma2(acc2[i][o], av[i], bs[o]);
        }
#pragma unroll
        for (int o=0;o<8;o++){
            float bias = b2s[tx*8+o];
            float pm = -3.4e38f;
#pragma unroll
            for (int i=0;i<4;i++){
                float lo, hi; unpack2(acc2[i][o], lo, hi);
                pm = fmaxf(pm, leaky(lo + bias));
                pm = fmaxf(pm, leaky(hi + bias));
            }
            red[ty*128 + tx*8 + o] = pm;
        }
    }
    __syncthreads();

    for (int e=tid; e<1024; e+=256){
        int o = e & 127;
        int p = e >> 7;
        float v = fmaxf(red[(2*p)*128 + o], red[(2*p+1)*128 + o]);
        out[((long)(b*128 + o))*NP + n0 + p] = v;
    }
}

extern "C" void kernel_launch(void* const* d_in, const int* in_sizes, int n_in,
                              void* d_out, int out_size){
    const float* feat = (const float*)d_in[0];
    const float* pos  = (const float*)d_in[1];
    const float* Wn   = (const float*)d_in[2];
    const float* bn   = (const float*)d_in[3];
    const float* We   = (const float*)d_in[4];
    const float* be   = (const float*)d_in[5];
    const float* W1   = (const float*)d_in[6];
    const float* b1   = (const float*)d_in[7];
    const float* W2   = (const float*)d_in[8];
    const float* b2   = (const float*)d_in[9];
    float* out = (float*)d_out;

    cudaFuncSetAttribute(u_kernel,  cudaFuncAttributeMaxDynamicSharedMemorySize, 65536);
    cudaFuncSetAttribute(edge_main, cudaFuncAttributeMaxDynamicSharedMemorySize, 98304);

    prep_kernel<<<80,256>>>(Wn, We, W1, W2);
    knn_pass1<<<256,256>>>(pos);
    knn_pass2<<<512,256>>>(pos);
    knn_pass3<<<2048,256>>>(pos);
    u_kernel<<<128,256,65536>>>(feat);
    edge_main<<<2048,256,96000>>>(bn, be, b1, b2, out);
}